// round 10
// baseline (speedup 1.0000x reference)
#include <cuda_runtime.h>
#include <cuda_bf16.h>
#include <cstdint>

// ---------------------------------------------------------------------------
// Conv_DCFD on sm_100 (no tcgen05 in this toolchain): conv1, conv2 and the
// final 1x1 GEMM all run on the tensor pipe via mma.sync tf32 (rna-rounded).
// R10: k3a+k3b fused into k3f -- bases_out A built in smem, never hits DRAM.
// Shapes: N=16,H=64,W=64,C=128, inter=64, bases=36, M=6, O=256
// ---------------------------------------------------------------------------

#define NB   16
#define HH   64
#define WW   64
#define CIN  128
#define CMID 64
#define BSZ  36
#define OO   256

// scratch (no cudaMalloc allowed)
__device__ float g_h   [NB * HH * WW * CMID];     // 16.8 MB
__device__ float g_dyn [NB * HH * WW * 54];       // 14.2 MB
__device__ float g_Bt  [OO * 768];                // 768 KB (B^T, tf32-rounded)
__device__ float g_W1t [9 * CMID * CIN];          // w1^T per tap, tf32
__device__ float g_W2t [48 * 576];                // w2^T co-major (pad 36->48), tf32

__device__ __forceinline__ void cp_async16(void* smem_dst, const void* gmem_src) {
    unsigned s = (unsigned)__cvta_generic_to_shared(smem_dst);
    asm volatile("cp.async.cg.shared.global [%0], [%1], 16;\n" :: "r"(s), "l"(gmem_src));
}
__device__ __forceinline__ void cp_commit() { asm volatile("cp.async.commit_group;\n"); }
template<int N> __device__ __forceinline__ void cp_wait() {
    asm volatile("cp.async.wait_group %0;\n" :: "n"(N));
}
__device__ __forceinline__ uint32_t tf32_rna(float v) {
    uint32_t r;
    asm("cvt.rna.tf32.f32 %0, %1;" : "=r"(r) : "f"(v));
    return r;
}
__device__ __forceinline__ void mma_tf32(float* d, const uint32_t* a, const uint32_t* b) {
    asm volatile(
        "mma.sync.aligned.m16n8k8.row.col.f32.tf32.tf32.f32 "
        "{%0,%1,%2,%3}, {%4,%5,%6,%7}, {%8,%9}, {%0,%1,%2,%3};"
        : "+f"(d[0]), "+f"(d[1]), "+f"(d[2]), "+f"(d[3])
        : "r"(a[0]), "r"(a[1]), "r"(a[2]), "r"(a[3]), "r"(b[0]), "r"(b[1]));
}

// ===========================================================================
// prep kernels: transpose + tf32-round weights
// ===========================================================================
__global__ void prepW_kernel(const float* __restrict__ w1) {
    const int bx = blockIdx.x;          // kk*64+co (576)
    const int t  = threadIdx.x;         // ci (128)
    const int kk = bx >> 6, co = bx & 63;
    g_W1t[bx * 128 + t] = __uint_as_float(tf32_rna(w1[(kk * 128 + t) * 64 + co]));
}

__global__ void prepW2_kernel(const float* __restrict__ w2) {
    const int n = blockIdx.x;           // 0..47 (co, padded)
    const int k = threadIdx.x;          // 0..575 (kk*64+ci)
    float v = 0.f;
    if (n < BSZ) {
        const int kk = k >> 6, ci = k & 63;
        v = w2[(kk * 64 + ci) * BSZ + n];
    }
    g_W2t[n * 576 + k] = __uint_as_float(tf32_rna(v));
}

__global__ void prepB_kernel(const float* __restrict__ coef) {
    const int n = blockIdx.x;
    const int t = threadIdx.x;
    #pragma unroll
    for (int q = 0; q < 3; q++) {
        int k = q * 256 + t;
        g_Bt[n * 768 + k] = __uint_as_float(tf32_rna(coef[k * OO + n]));
    }
}

// ===========================================================================
// Kernel 1: conv1 via mma.sync tf32 + BN(axis=H) + ReLU -> g_h   (passing)
// grid = 512 (2 rows), block 512 (16 warps, 4m x 4n), warp 32px x 16co.
// ===========================================================================
#define C1_SSTR  132
#define C1_SLAB  (264 * C1_SSTR)
#define C1_WSTR  140
#define C1_WCH   (CMID * C1_WSTR)
#define C1_SMEM  ((C1_SLAB + 2 * C1_WCH) * 4)

__global__ __launch_bounds__(512, 1)
void conv1_kernel(const float* __restrict__ x, const float* __restrict__ b1,
                  const float* __restrict__ gamma1, const float* __restrict__ beta1) {
    extern __shared__ float sm[];
    float* slab = sm;
    float* wbuf = sm + C1_SLAB;

    const int t  = threadIdx.x;
    const int bx = blockIdx.x;
    const int nb = bx >> 5;
    const int h0 = (bx & 31) << 1;

    for (int i = t; i < 2048; i += 512) {
        int row = i >> 5, seg = i & 31;
        cp_async16(wbuf + row * C1_WSTR + seg * 4, g_W1t + row * 128 + seg * 4);
    }
    cp_commit();

    const float4* x4 = (const float4*)x;
    for (int idx = t; idx < 4 * 66 * 32; idx += 512) {
        int ci4 = idx & 31;
        int col = (idx >> 5) % 66;
        int r   = idx / (32 * 66);
        int hh  = h0 + r - 1, ww = col - 1;
        float4 v = make_float4(0.f, 0.f, 0.f, 0.f);
        if (hh >= 0 && hh < HH && ww >= 0 && ww < WW)
            v = x4[((((nb << 6) + hh) << 6) + ww) * 32 + ci4];
        float4 o;
        o.x = __uint_as_float(tf32_rna(v.x));
        o.y = __uint_as_float(tf32_rna(v.y));
        o.z = __uint_as_float(tf32_rna(v.z));
        o.w = __uint_as_float(tf32_rna(v.w));
        *(float4*)(slab + (r * 66 + col) * C1_SSTR + ci4 * 4) = o;
    }
    cp_wait<0>();
    __syncthreads();

    const int wid  = t >> 5;
    const int lane = t & 31;
    const int g    = lane >> 2;
    const int t4   = lane & 3;
    const int wm   = wid >> 2;
    const int wn   = wid & 3;
    const int p0   = wm << 5;
    const int r    = p0 >> 6;
    const int col0 = p0 & 63;

    float d[2][2][4] = {};

    for (int kk = 0; kk < 9; kk++) {
        const float* wb = wbuf + (kk & 1) * C1_WCH;
        if (kk < 8) {
            float* dst = wbuf + ((kk + 1) & 1) * C1_WCH;
            const float* src = g_W1t + (kk + 1) * 8192;
            for (int i = t; i < 2048; i += 512) {
                int row = i >> 5, seg = i & 31;
                cp_async16(dst + row * C1_WSTR + seg * 4, src + row * 128 + seg * 4);
            }
            cp_commit();
        }
        const int kh = kk / 3, kw = kk % 3;
        const float* arow = slab + ((r + kh) * 66 + kw + col0 + g) * C1_SSTR;

        #pragma unroll
        for (int kt = 0; kt < 16; kt++) {
            const int k0 = kt << 3;
            uint32_t a[2][4], b[2][2];
            #pragma unroll
            for (int mi = 0; mi < 2; mi++) {
                const float* ap = arow + (mi << 4) * C1_SSTR + k0 + t4;
                a[mi][0] = __float_as_uint(ap[0]);
                a[mi][1] = __float_as_uint(ap[8 * C1_SSTR]);
                a[mi][2] = __float_as_uint(ap[4]);
                a[mi][3] = __float_as_uint(ap[8 * C1_SSTR + 4]);
            }
            #pragma unroll
            for (int ni = 0; ni < 2; ni++) {
                const float* bp = wb + ((wn << 4) + (ni << 3) + g) * C1_WSTR + k0 + t4;
                b[ni][0] = __float_as_uint(bp[0]);
                b[ni][1] = __float_as_uint(bp[4]);
            }
            #pragma unroll
            for (int mi = 0; mi < 2; mi++)
                #pragma unroll
                for (int ni = 0; ni < 2; ni++)
                    mma_tf32(d[mi][ni], a[mi], b[ni]);
        }
        cp_wait<0>();
        __syncthreads();
    }

    const float invs = rsqrtf(1.0f + 1e-3f);
    const float gs = gamma1[h0 + r] * invs;
    const float bb = beta1[h0 + r];
    #pragma unroll
    for (int mi = 0; mi < 2; mi++) {
        const int p = p0 + (mi << 4) + g;
        float* r0 = g_h + ((size_t)(bx << 7) + p) * CMID;
        float* r1 = r0 + 8 * CMID;
        #pragma unroll
        for (int ni = 0; ni < 2; ni++) {
            const int c = (wn << 4) + (ni << 3) + (t4 << 1);
            const float bc0 = b1[c], bc1 = b1[c + 1];
            float2 v0, v1;
            v0.x = fmaxf(fmaf(d[mi][ni][0] + bc0, gs, bb), 0.f);
            v0.y = fmaxf(fmaf(d[mi][ni][1] + bc1, gs, bb), 0.f);
            v1.x = fmaxf(fmaf(d[mi][ni][2] + bc0, gs, bb), 0.f);
            v1.y = fmaxf(fmaf(d[mi][ni][3] + bc1, gs, bb), 0.f);
            *(float2*)(r0 + c) = v0;
            *(float2*)(r1 + c) = v1;
        }
    }
}

// ===========================================================================
// Kernel 2: conv2 via mma.sync tf32 + BN + ReLU + xFB -> g_dyn   (passing)
// grid = 256 (4 rows), block 512 (16 warps, 8m x 2n), warp 32px x 24co.
// ===========================================================================
#define C2_SSTR  68
#define C2_SLAB  (396 * C2_SSTR)
#define C2_WSTR  580
#define C2_WS    (48 * C2_WSTR)
#define C2_SMEM  ((C2_SLAB + C2_WS + 64) * 4)

__global__ __launch_bounds__(512, 1)
void conv2_kernel(const float* __restrict__ b2, const float* __restrict__ gamma2,
                  const float* __restrict__ beta2, const float* __restrict__ bases) {
    extern __shared__ float sm[];
    float* slab = sm;
    float* ws   = sm + C2_SLAB;
    float* bss  = sm + C2_SLAB + C2_WS;

    const int t  = threadIdx.x;
    const int bx = blockIdx.x;
    const int nb = bx >> 4;
    const int h0 = (bx & 15) << 2;

    for (int i = t; i < 6912; i += 512) {
        int row = i / 144, seg = i % 144;
        cp_async16(ws + row * C2_WSTR + seg * 4, g_W2t + row * 576 + seg * 4);
    }
    cp_commit();
    if (t < 54) bss[t] = bases[t];

    const float4* h4 = (const float4*)g_h;
    for (int idx = t; idx < 6 * 66 * 16; idx += 512) {
        int seg = idx & 15;
        int pos = idx >> 4;
        int r   = pos / 66, col = pos % 66;
        int hh  = h0 + r - 1, ww = col - 1;
        float4 v = make_float4(0.f, 0.f, 0.f, 0.f);
        if (hh >= 0 && hh < HH && ww >= 0 && ww < WW)
            v = h4[(size_t)((((nb << 6) + hh) << 6) + ww) * 16 + seg];
        *(float4*)(slab + (r * 66 + col) * C2_SSTR + seg * 4) = v;
    }
    cp_wait<0>();
    __syncthreads();

    const int wid  = t >> 5;
    const int lane = t & 31;
    const int g    = lane >> 2;
    const int t4   = lane & 3;
    const int wm   = wid >> 1;
    const int wn   = wid & 1;
    const int p0   = wm << 5;
    const int r    = p0 >> 6;
    const int wcol = p0 & 63;

    float d[2][3][4] = {};

    #pragma unroll
    for (int kk = 0; kk < 9; kk++) {
        const int kh = kk / 3, kw = kk % 3;
        const float* arow = slab + ((r + kh) * 66 + kw + wcol + g) * C2_SSTR;
        const float* brow = ws + (wn * 24 + g) * C2_WSTR + kk * 64;
        #pragma unroll
        for (int kt = 0; kt < 8; kt++) {
            const int k0 = kt << 3;
            uint32_t a[2][4], b[3][2];
            #pragma unroll
            for (int mi = 0; mi < 2; mi++) {
                const float* ap = arow + (mi << 4) * C2_SSTR + k0 + t4;
                a[mi][0] = __float_as_uint(ap[0]);
                a[mi][1] = __float_as_uint(ap[8 * C2_SSTR]);
                a[mi][2] = __float_as_uint(ap[4]);
                a[mi][3] = __float_as_uint(ap[8 * C2_SSTR + 4]);
            }
            #pragma unroll
            for (int ni = 0; ni < 3; ni++) {
                const float* bp = brow + (ni << 3) * C2_WSTR + k0 + t4;
                b[ni][0] = __float_as_uint(bp[0]);
                b[ni][1] = __float_as_uint(bp[4]);
            }
            #pragma unroll
            for (int mi = 0; mi < 2; mi++)
                #pragma unroll
                for (int ni = 0; ni < 3; ni++)
                    mma_tf32(d[mi][ni], a[mi], b[ni]);
        }
    }
    __syncthreads();

    float* bfs = ws;
    const float invs = rsqrtf(1.0f + 1e-3f);
    const float gs = gamma2[h0 + r] * invs;
    const float bb = beta2[h0 + r];
    #pragma unroll
    for (int mi = 0; mi < 2; mi++) {
        const int p = p0 + (mi << 4) + g;
        #pragma unroll
        for (int ni = 0; ni < 3; ni++) {
            const int c = wn * 24 + (ni << 3) + (t4 << 1);
            if (c < BSZ) {
                const float bj0 = b2[c], bj1 = b2[c + 1];
                bfs[p * 37 + c]           = fmaxf(fmaf(d[mi][ni][0] + bj0, gs, bb), 0.f);
                bfs[p * 37 + c + 1]       = fmaxf(fmaf(d[mi][ni][1] + bj1, gs, bb), 0.f);
                bfs[(p + 8) * 37 + c]     = fmaxf(fmaf(d[mi][ni][2] + bj0, gs, bb), 0.f);
                bfs[(p + 8) * 37 + c + 1] = fmaxf(fmaf(d[mi][ni][3] + bj1, gs, bb), 0.f);
            }
        }
    }
    __syncthreads();

    const int pp = t >> 1;
    const int half = t & 1;
    const float* bf = bfs + pp * 37;
    const int rr = pp >> 6, pw = pp & 63;
    float* outp = g_dyn + (size_t)((((nb << 6) + h0 + rr) << 6) + pw) * 54;
    #pragma unroll
    for (int q = 0; q < 27; q++) {
        int idx = half * 27 + q;
        int m = idx / 9, l = idx % 9;
        float s = 0.f;
        #pragma unroll
        for (int k = 0; k < 6; k++) s = fmaf(bf[m * 6 + k], bss[k * 9 + l], s);
        outp[idx] = s;
    }
}

// ===========================================================================
// Kernel 3 FUSED (k3f): bases_out A built in smem + tf32 GEMM + bias -> out
// grid = 1024 (1 image row = 64 px), block 256 (8 warps: 2m x 4n; warp tile
// 32px x 64co, micro 2m x 8n -- k3b's proven inner loop, A-stride 100).
// K=768 as 8 channel-chunks of 96 (16 ch x 6 m); per chunk: build Asub from
// x-slab (k3a scramble) then 3 x 32-k GEMM substeps; B double-buffered
// cp.async from L2-resident g_Bt. No g_A traffic.
// ===========================================================================
#define F_SSTR 199
#define F_SLAB (CIN * F_SSTR)            // 25472 fl
#define F_ASTR 100
#define F_ASUB (64 * F_ASTR)             // 6400 fl
#define F_BSTR 36
#define F_BCH  (256 * F_BSTR)            // 9216 fl
#define F_DSTR 55
#define F_DYN  (64 * F_DSTR)             // 3520 fl
#define F_SMEM ((F_SLAB + F_ASUB + 2 * F_BCH + F_DYN) * 4)   // 215296 B

__global__ __launch_bounds__(256, 1)
void k3f_kernel(const float* __restrict__ x, const float* __restrict__ bias,
                float* __restrict__ out) {
    extern __shared__ float sm[];
    float* slab = sm;
    float* asub = sm + F_SLAB;
    float* Bs[2] = { sm + F_SLAB + F_ASUB, sm + F_SLAB + F_ASUB + F_BCH };
    float* dyns = sm + F_SLAB + F_ASUB + 2 * F_BCH;

    const int t  = threadIdx.x;
    const int bx = blockIdx.x;
    const int nb = bx >> 6;
    const int h  = bx & 63;

    // prefetch B substep 0 (k = 0..31)
    for (int i = t; i < 2048; i += 256) {
        int row = i >> 3, seg = i & 7;
        cp_async16(Bs[0] + row * F_BSTR + seg * 4, g_Bt + row * 768 + seg * 4);
    }
    cp_commit();

    // x slab: rows h-1..h+1 (3), cols -1..64 (66), 128 ci, [ci][199] transposed
    const float4* x4 = (const float4*)x;
    for (int idx = t; idx < 3 * 66 * 32; idx += 256) {
        int ci4 = idx & 31;
        int col = (idx >> 5) % 66;
        int r   = idx / (32 * 66);
        int hh  = h + r - 1, ww = col - 1;
        float4 v = make_float4(0.f, 0.f, 0.f, 0.f);
        if (hh >= 0 && hh < HH && ww >= 0 && ww < WW)
            v = x4[((((nb << 6) + hh) << 6) + ww) * 32 + ci4];
        int so = r * 66 + col;
        slab[(ci4 * 4 + 0) * F_SSTR + so] = v.x;
        slab[(ci4 * 4 + 1) * F_SSTR + so] = v.y;
        slab[(ci4 * 4 + 2) * F_SSTR + so] = v.z;
        slab[(ci4 * 4 + 3) * F_SSTR + so] = v.w;
    }
    // dyn: 64 px x 54, stored stride 55
    {
        const float* dsrc = g_dyn + (size_t)(bx << 6) * 54;
        for (int i = t; i < 64 * 54; i += 256) {
            int p = i / 54, q = i % 54;
            dyns[p * F_DSTR + q] = dsrc[i];
        }
    }
    __syncthreads();

    const int wid  = t >> 5;
    const int lane = t & 31;
    const int g    = lane >> 2;
    const int t4   = lane & 3;
    const int wm   = wid >> 2;           // 0..1 (32-px group)
    const int wn   = wid & 3;            // 0..3 (64-co group)
    const int m0   = wm << 5;
    const int n0   = wn << 6;

    // build mapping: bpx = t>>2 (0..63), bc4 = (t&3)*4 (4 channels each)
    const int bpx = t >> 2;
    const int bc4 = (t & 3) << 2;

    float d[2][8][4] = {};
    int gsub = 0;

    for (int chunk = 0; chunk < 8; chunk++) {
        // ---- build Asub[64][96] for channels chunk*16 .. +15 ----
        {
            float dv[54];
            #pragma unroll
            for (int i = 0; i < 54; i++) dv[i] = dyns[bpx * F_DSTR + i];
            #pragma unroll
            for (int j = 0; j < 4; j++) {
                const int chl = bc4 + j;
                const int ch  = (chunk << 4) + chl;
                float pt[9];
                #pragma unroll
                for (int l = 0; l < 9; l++) {
                    const int f  = ch * 9 + l;
                    const int cc = f & 127;
                    const int pi = f >> 7;
                    pt[l] = slab[cc * F_SSTR + (pi / 3) * 66 + (pi % 3) + bpx];
                }
                #pragma unroll
                for (int m = 0; m < 6; m++) {
                    float s = 0.f;
                    #pragma unroll
                    for (int l = 0; l < 9; l++) s = fmaf(dv[m * 9 + l], pt[l], s);
                    asub[bpx * F_ASTR + chl * 6 + m] = __uint_as_float(tf32_rna(s));
                }
            }
        }
        __syncthreads();

        // ---- 3 GEMM substeps of 32 k ----
        for (int s = 0; s < 3; s++, gsub++) {
            cp_wait<0>();
            __syncthreads();
            if (gsub < 23) {
                const int nx = gsub + 1;
                float* db = Bs[nx & 1];
                const float* src = g_Bt + nx * 32;
                for (int i = t; i < 2048; i += 256) {
                    int row = i >> 3, seg = i & 7;
                    cp_async16(db + row * F_BSTR + seg * 4, src + row * 768 + seg * 4);
                }
                cp_commit();
            }
            const float* Ac = asub + s * 32;
            const float* Bc = Bs[gsub & 1];

            #pragma unroll
            for (int kt = 0; kt < 4; kt++) {
                const int k0 = kt << 3;
                uint32_t a[2][4], b[8][2];
                #pragma unroll
                for (int mi = 0; mi < 2; mi++) {
                    const float* ap = Ac + (m0 + (mi << 4) + g) * F_ASTR + k0 + t4;
                    a[mi][0] = __float_as_uint(ap[0]);
                    a[mi][1] = __float_as_uint(ap[8 * F_ASTR]);
                    a[mi][2] = __float_as_uint(ap[4]);
                    a[mi][3] = __float_as_uint(ap[8 * F_ASTR + 4]);
                }
                #pragma unroll
                for (int ni = 0; ni < 8; ni++) {
                    const float* bp = Bc + (n0 + (ni << 3) + g) * F_BSTR + k0 + t4;
                    b[ni][0] = __float_as_uint(bp[0]);
                    b[ni][1] = __float_as_uint(bp[4]);
                }
                #pragma unroll
                for (int mi = 0; mi < 2; mi++)
                    #pragma unroll
                    for (int ni = 0; ni < 8; ni++)
                        mma_tf32(d[mi][ni], a[mi], b[ni]);
            }
            __syncthreads();
        }
    }

    // epilogue: bias + store
    const size_t rbase = (size_t)(bx << 6) + m0;
    const int    cbase = n0 + (t4 << 1);
    #pragma unroll
    for (int mi = 0; mi < 2; mi++) {
        float* r0 = out + (rbase + (mi << 4) + g) * OO;
        float* r1 = r0 + 8 * OO;
        #pragma unroll
        for (int ni = 0; ni < 8; ni++) {
            const int c = cbase + (ni << 3);
            const float b0 = bias[c], b1 = bias[c + 1];
            *(float2*)(r0 + c) = make_float2(d[mi][ni][0] + b0, d[mi][ni][1] + b1);
            *(float2*)(r1 + c) = make_float2(d[mi][ni][2] + b0, d[mi][ni][3] + b1);
        }
    }
}

// ===========================================================================
extern "C" void kernel_launch(void* const* d_in, const int* in_sizes, int n_in,
                              void* d_out, int out_size) {
    const float* x      = (const float*)d_in[0];
    const float* w1     = (const float*)d_in[1];
    const float* b1     = (const float*)d_in[2];
    const float* gamma1 = (const float*)d_in[3];
    const float* beta1  = (const float*)d_in[4];
    const float* w2     = (const float*)d_in[5];
    const float* b2     = (const float*)d_in[6];
    const float* gamma2 = (const float*)d_in[7];
    const float* beta2  = (const float*)d_in[8];
    const float* bases  = (const float*)d_in[9];
    const float* coef   = (const float*)d_in[10];
    const float* bias   = (const float*)d_in[11];
    float* out = (float*)d_out;

    cudaFuncSetAttribute(conv1_kernel, cudaFuncAttributeMaxDynamicSharedMemorySize, C1_SMEM);
    cudaFuncSetAttribute(conv2_kernel, cudaFuncAttributeMaxDynamicSharedMemorySize, C2_SMEM);
    cudaFuncSetAttribute(k3f_kernel,   cudaFuncAttributeMaxDynamicSharedMemorySize, F_SMEM);

    prepW_kernel <<<576, 128>>>(w1);
    prepW2_kernel<<<48,  576>>>(w2);
    prepB_kernel <<<OO,  256>>>(coef);
    conv1_kernel<<<NB * HH / 2, 512, C1_SMEM>>>(x, b1, gamma1, beta1);
    conv2_kernel<<<NB * HH / 4, 512, C2_SMEM>>>(b2, gamma2, beta2, bases);
    k3f_kernel  <<<NB * HH,     256, F_SMEM>>>(x, bias, out);
}

// round 11
// speedup vs baseline: 1.1553x; 1.1553x over previous
#include <cuda_runtime.h>
#include <cuda_bf16.h>
#include <cstdint>

// ---------------------------------------------------------------------------
// Conv_DCFD on sm_100 (no tcgen05 in this toolchain): conv1, conv2 and the
// final 1x1 GEMM all run on the tensor pipe via mma.sync tf32 (rna-rounded).
// R11: fusion reverted (regressed); conv1 retiled to 32x32 warp tiles
// (2.0 -> fewer LDS per MMA in the mainloop).
// Shapes: N=16,H=64,W=64,C=128, inter=64, bases=36, M=6, O=256
// ---------------------------------------------------------------------------

#define NB   16
#define HH   64
#define WW   64
#define CIN  128
#define CMID 64
#define BSZ  36
#define OO   256

// scratch (no cudaMalloc allowed)
__device__ float g_h   [NB * HH * WW * CMID];     // 16.8 MB
__device__ float g_dyn [NB * HH * WW * 54];       // 14.2 MB
__device__ float g_A   [NB * HH * WW * 768];      // 201 MB (tf32-rounded)
__device__ float g_Bt  [OO * 768];                // 768 KB (B^T, tf32-rounded)
__device__ float g_W1t [9 * CMID * CIN];          // w1^T per tap, tf32
__device__ float g_W2t [48 * 576];                // w2^T co-major (pad 36->48), tf32

__device__ __forceinline__ void cp_async16(void* smem_dst, const void* gmem_src) {
    unsigned s = (unsigned)__cvta_generic_to_shared(smem_dst);
    asm volatile("cp.async.cg.shared.global [%0], [%1], 16;\n" :: "r"(s), "l"(gmem_src));
}
__device__ __forceinline__ void cp_commit() { asm volatile("cp.async.commit_group;\n"); }
template<int N> __device__ __forceinline__ void cp_wait() {
    asm volatile("cp.async.wait_group %0;\n" :: "n"(N));
}
__device__ __forceinline__ uint32_t tf32_rna(float v) {
    uint32_t r;
    asm("cvt.rna.tf32.f32 %0, %1;" : "=r"(r) : "f"(v));
    return r;
}
__device__ __forceinline__ void mma_tf32(float* d, const uint32_t* a, const uint32_t* b) {
    asm volatile(
        "mma.sync.aligned.m16n8k8.row.col.f32.tf32.tf32.f32 "
        "{%0,%1,%2,%3}, {%4,%5,%6,%7}, {%8,%9}, {%0,%1,%2,%3};"
        : "+f"(d[0]), "+f"(d[1]), "+f"(d[2]), "+f"(d[3])
        : "r"(a[0]), "r"(a[1]), "r"(a[2]), "r"(a[3]), "r"(b[0]), "r"(b[1]));
}

// ===========================================================================
// prep kernels: transpose + tf32-round weights
// ===========================================================================
__global__ void prepW_kernel(const float* __restrict__ w1) {
    const int bx = blockIdx.x;          // kk*64+co (576)
    const int t  = threadIdx.x;         // ci (128)
    const int kk = bx >> 6, co = bx & 63;
    g_W1t[bx * 128 + t] = __uint_as_float(tf32_rna(w1[(kk * 128 + t) * 64 + co]));
}

__global__ void prepW2_kernel(const float* __restrict__ w2) {
    const int n = blockIdx.x;           // 0..47 (co, padded)
    const int k = threadIdx.x;          // 0..575 (kk*64+ci)
    float v = 0.f;
    if (n < BSZ) {
        const int kk = k >> 6, ci = k & 63;
        v = w2[(kk * 64 + ci) * BSZ + n];
    }
    g_W2t[n * 576 + k] = __uint_as_float(tf32_rna(v));
}

__global__ void prepB_kernel(const float* __restrict__ coef) {
    const int n = blockIdx.x;
    const int t = threadIdx.x;
    #pragma unroll
    for (int q = 0; q < 3; q++) {
        int k = q * 256 + t;
        g_Bt[n * 768 + k] = __uint_as_float(tf32_rna(coef[k * OO + n]));
    }
}

// ===========================================================================
// Kernel 1: conv1 via mma.sync tf32 + BN(axis=H) + ReLU -> g_h
// grid = 512 (nb, h0 = 2 rows = 128 px), block 256 (8 warps, 4m x 2n),
// warp tile 32px x 32co (8 LDS : 8 MMA per k-slice, was 12:4).
// slab: x rows h0-1..h0+2 (4x66), [row66][ci] str 132; wbuf [co][ci] str 140.
// ===========================================================================
#define C1_SSTR  132
#define C1_SLAB  (264 * C1_SSTR)        // 34848 floats
#define C1_WSTR  140
#define C1_WCH   (CMID * C1_WSTR)       // 8960 floats
#define C1_SMEM  ((C1_SLAB + 2 * C1_WCH) * 4)   // 211072 B

__global__ __launch_bounds__(256, 1)
void conv1_kernel(const float* __restrict__ x, const float* __restrict__ b1,
                  const float* __restrict__ gamma1, const float* __restrict__ beta1) {
    extern __shared__ float sm[];
    float* slab = sm;
    float* wbuf = sm + C1_SLAB;

    const int t  = threadIdx.x;
    const int bx = blockIdx.x;
    const int nb = bx >> 5;
    const int h0 = (bx & 31) << 1;

    // preload weight chunk 0 (64 co rows x 32 float4 segs)
    for (int i = t; i < 2048; i += 256) {
        int row = i >> 5, seg = i & 31;
        cp_async16(wbuf + row * C1_WSTR + seg * 4, g_W1t + row * 128 + seg * 4);
    }
    cp_commit();

    // slab: rows h0-1..h0+2 (4), cols -1..64 (66), 128 ci, tf32-rounded
    const float4* x4 = (const float4*)x;
    for (int idx = t; idx < 4 * 66 * 32; idx += 256) {
        int ci4 = idx & 31;
        int col = (idx >> 5) % 66;
        int r   = idx / (32 * 66);
        int hh  = h0 + r - 1, ww = col - 1;
        float4 v = make_float4(0.f, 0.f, 0.f, 0.f);
        if (hh >= 0 && hh < HH && ww >= 0 && ww < WW)
            v = x4[((((nb << 6) + hh) << 6) + ww) * 32 + ci4];
        float4 o;
        o.x = __uint_as_float(tf32_rna(v.x));
        o.y = __uint_as_float(tf32_rna(v.y));
        o.z = __uint_as_float(tf32_rna(v.z));
        o.w = __uint_as_float(tf32_rna(v.w));
        *(float4*)(slab + (r * 66 + col) * C1_SSTR + ci4 * 4) = o;
    }
    cp_wait<0>();
    __syncthreads();

    const int wid  = t >> 5;
    const int lane = t & 31;
    const int g    = lane >> 2;
    const int t4   = lane & 3;
    const int wm   = wid >> 1;           // 0..3  (32-px group)
    const int wn   = wid & 1;            // 0..1  (32-co group)
    const int p0   = wm << 5;            // pixel base 0..96
    const int r    = p0 >> 6;            // image row within pair (0/1)
    const int col0 = p0 & 63;

    float d[2][4][4] = {};

    for (int kk = 0; kk < 9; kk++) {
        const float* wb = wbuf + (kk & 1) * C1_WCH;
        if (kk < 8) {
            float* dst = wbuf + ((kk + 1) & 1) * C1_WCH;
            const float* src = g_W1t + (kk + 1) * 8192;
            for (int i = t; i < 2048; i += 256) {
                int row = i >> 5, seg = i & 31;
                cp_async16(dst + row * C1_WSTR + seg * 4, src + row * 128 + seg * 4);
            }
            cp_commit();
        }
        const int kh = kk / 3, kw = kk % 3;
        const float* arow = slab + ((r + kh) * 66 + kw + col0 + g) * C1_SSTR;

        #pragma unroll
        for (int kt = 0; kt < 16; kt++) {
            const int k0 = kt << 3;
            uint32_t a[2][4], b[4][2];
            #pragma unroll
            for (int mi = 0; mi < 2; mi++) {
                const float* ap = arow + (mi << 4) * C1_SSTR + k0 + t4;
                a[mi][0] = __float_as_uint(ap[0]);
                a[mi][1] = __float_as_uint(ap[8 * C1_SSTR]);
                a[mi][2] = __float_as_uint(ap[4]);
                a[mi][3] = __float_as_uint(ap[8 * C1_SSTR + 4]);
            }
            #pragma unroll
            for (int ni = 0; ni < 4; ni++) {
                const float* bp = wb + ((wn << 5) + (ni << 3) + g) * C1_WSTR + k0 + t4;
                b[ni][0] = __float_as_uint(bp[0]);
                b[ni][1] = __float_as_uint(bp[4]);
            }
            #pragma unroll
            for (int mi = 0; mi < 2; mi++)
                #pragma unroll
                for (int ni = 0; ni < 4; ni++)
                    mma_tf32(d[mi][ni], a[mi], b[ni]);
        }
        cp_wait<0>();
        __syncthreads();
    }

    const float invs = rsqrtf(1.0f + 1e-3f);
    const float gs = gamma1[h0 + r] * invs;
    const float bb = beta1[h0 + r];
    #pragma unroll
    for (int mi = 0; mi < 2; mi++) {
        const int p = p0 + (mi << 4) + g;
        float* r0 = g_h + ((size_t)(bx << 7) + p) * CMID;
        float* r1 = r0 + 8 * CMID;
        #pragma unroll
        for (int ni = 0; ni < 4; ni++) {
            const int c = (wn << 5) + (ni << 3) + (t4 << 1);
            const float bc0 = b1[c], bc1 = b1[c + 1];
            float2 v0, v1;
            v0.x = fmaxf(fmaf(d[mi][ni][0] + bc0, gs, bb), 0.f);
            v0.y = fmaxf(fmaf(d[mi][ni][1] + bc1, gs, bb), 0.f);
            v1.x = fmaxf(fmaf(d[mi][ni][2] + bc0, gs, bb), 0.f);
            v1.y = fmaxf(fmaf(d[mi][ni][3] + bc1, gs, bb), 0.f);
            *(float2*)(r0 + c) = v0;
            *(float2*)(r1 + c) = v1;
        }
    }
}

// ===========================================================================
// Kernel 2: conv2 via mma.sync tf32 + BN + ReLU + xFB -> g_dyn   (passing)
// grid = 256 (4 rows), block 512 (16 warps, 8m x 2n), warp 32px x 24co.
// ===========================================================================
#define C2_SSTR  68
#define C2_SLAB  (396 * C2_SSTR)
#define C2_WSTR  580
#define C2_WS    (48 * C2_WSTR)
#define C2_SMEM  ((C2_SLAB + C2_WS + 64) * 4)

__global__ __launch_bounds__(512, 1)
void conv2_kernel(const float* __restrict__ b2, const float* __restrict__ gamma2,
                  const float* __restrict__ beta2, const float* __restrict__ bases) {
    extern __shared__ float sm[];
    float* slab = sm;
    float* ws   = sm + C2_SLAB;
    float* bss  = sm + C2_SLAB + C2_WS;

    const int t  = threadIdx.x;
    const int bx = blockIdx.x;
    const int nb = bx >> 4;
    const int h0 = (bx & 15) << 2;

    for (int i = t; i < 6912; i += 512) {
        int row = i / 144, seg = i % 144;
        cp_async16(ws + row * C2_WSTR + seg * 4, g_W2t + row * 576 + seg * 4);
    }
    cp_commit();
    if (t < 54) bss[t] = bases[t];

    const float4* h4 = (const float4*)g_h;
    for (int idx = t; idx < 6 * 66 * 16; idx += 512) {
        int seg = idx & 15;
        int pos = idx >> 4;
        int r   = pos / 66, col = pos % 66;
        int hh  = h0 + r - 1, ww = col - 1;
        float4 v = make_float4(0.f, 0.f, 0.f, 0.f);
        if (hh >= 0 && hh < HH && ww >= 0 && ww < WW)
            v = h4[(size_t)((((nb << 6) + hh) << 6) + ww) * 16 + seg];
        *(float4*)(slab + (r * 66 + col) * C2_SSTR + seg * 4) = v;
    }
    cp_wait<0>();
    __syncthreads();

    const int wid  = t >> 5;
    const int lane = t & 31;
    const int g    = lane >> 2;
    const int t4   = lane & 3;
    const int wm   = wid >> 1;
    const int wn   = wid & 1;
    const int p0   = wm << 5;
    const int r    = p0 >> 6;
    const int wcol = p0 & 63;

    float d[2][3][4] = {};

    #pragma unroll
    for (int kk = 0; kk < 9; kk++) {
        const int kh = kk / 3, kw = kk % 3;
        const float* arow = slab + ((r + kh) * 66 + kw + wcol + g) * C2_SSTR;
        const float* brow = ws + (wn * 24 + g) * C2_WSTR + kk * 64;
        #pragma unroll
        for (int kt = 0; kt < 8; kt++) {
            const int k0 = kt << 3;
            uint32_t a[2][4], b[3][2];
            #pragma unroll
            for (int mi = 0; mi < 2; mi++) {
                const float* ap = arow + (mi << 4) * C2_SSTR + k0 + t4;
                a[mi][0] = __float_as_uint(ap[0]);
                a[mi][1] = __float_as_uint(ap[8 * C2_SSTR]);
                a[mi][2] = __float_as_uint(ap[4]);
                a[mi][3] = __float_as_uint(ap[8 * C2_SSTR + 4]);
            }
            #pragma unroll
            for (int ni = 0; ni < 3; ni++) {
                const float* bp = brow + (ni << 3) * C2_WSTR + k0 + t4;
                b[ni][0] = __float_as_uint(bp[0]);
                b[ni][1] = __float_as_uint(bp[4]);
            }
            #pragma unroll
            for (int mi = 0; mi < 2; mi++)
                #pragma unroll
                for (int ni = 0; ni < 3; ni++)
                    mma_tf32(d[mi][ni], a[mi], b[ni]);
        }
    }
    __syncthreads();

    float* bfs = ws;
    const float invs = rsqrtf(1.0f + 1e-3f);
    const float gs = gamma2[h0 + r] * invs;
    const float bb = beta2[h0 + r];
    #pragma unroll
    for (int mi = 0; mi < 2; mi++) {
        const int p = p0 + (mi << 4) + g;
        #pragma unroll
        for (int ni = 0; ni < 3; ni++) {
            const int c = wn * 24 + (ni << 3) + (t4 << 1);
            if (c < BSZ) {
                const float bj0 = b2[c], bj1 = b2[c + 1];
                bfs[p * 37 + c]           = fmaxf(fmaf(d[mi][ni][0] + bj0, gs, bb), 0.f);
                bfs[p * 37 + c + 1]       = fmaxf(fmaf(d[mi][ni][1] + bj1, gs, bb), 0.f);
                bfs[(p + 8) * 37 + c]     = fmaxf(fmaf(d[mi][ni][2] + bj0, gs, bb), 0.f);
                bfs[(p + 8) * 37 + c + 1] = fmaxf(fmaf(d[mi][ni][3] + bj1, gs, bb), 0.f);
            }
        }
    }
    __syncthreads();

    const int pp = t >> 1;
    const int half = t & 1;
    const float* bf = bfs + pp * 37;
    const int rr = pp >> 6, pw = pp & 63;
    float* outp = g_dyn + (size_t)((((nb << 6) + h0 + rr) << 6) + pw) * 54;
    #pragma unroll
    for (int q = 0; q < 27; q++) {
        int idx = half * 27 + q;
        int m = idx / 9, l = idx % 9;
        float s = 0.f;
        #pragma unroll
        for (int k = 0; k < 6; k++) s = fmaf(bf[m * 6 + k], bss[k * 9 + l], s);
        outp[idx] = s;
    }
}

// ===========================================================================
// Kernel 3a: bases_out A -> g_A[65536][768] (tf32-rounded)  (passing, R9)
// ===========================================================================
#define K3A_SSTR 199
#define K3A_SMEM (CIN * K3A_SSTR * 4)

__global__ __launch_bounds__(256, 2)
void k3a_kernel(const float* __restrict__ x) {
    extern __shared__ float sm[];
    float* slab = sm;

    const int t  = threadIdx.x;
    const int bx = blockIdx.x;
    const int nb = bx >> 6;
    const int h  = bx & 63;

    const float4* x4 = (const float4*)x;
    for (int idx = t; idx < 3 * 66 * 32; idx += 256) {
        int ci4 = idx & 31;
        int col = (idx >> 5) % 66;
        int r   = idx / (32 * 66);
        int hh  = h + r - 1, ww = col - 1;
        float4 v = make_float4(0.f, 0.f, 0.f, 0.f);
        if (hh >= 0 && hh < HH && ww >= 0 && ww < WW)
            v = x4[((((nb << 6) + hh) << 6) + ww) * 32 + ci4];
        int so = r * 66 + col;
        slab[(ci4 * 4 + 0) * K3A_SSTR + so] = v.x;
        slab[(ci4 * 4 + 1) * K3A_SSTR + so] = v.y;
        slab[(ci4 * 4 + 2) * K3A_SSTR + so] = v.z;
        slab[(ci4 * 4 + 3) * K3A_SSTR + so] = v.w;
    }
    __syncthreads();

    const int w    = t >> 5;
    const int lane = t & 31;

    for (int pp = 0; pp < 8; pp++) {
        const int p = (w << 3) + pp;
        const size_t pix = (size_t)(bx << 6) + p;
        const float* dp = g_dyn + pix * 54;
        float dv[54];
        #pragma unroll
        for (int i = 0; i < 54; i++) dv[i] = __ldg(dp + i);

        float* arow = g_A + pix * 768;
        #pragma unroll
        for (int j = 0; j < 4; j++) {
            const int ch = lane + (j << 5);
            float pt[9];
            #pragma unroll
            for (int l = 0; l < 9; l++) {
                const int f  = ch * 9 + l;
                const int cc = f & 127;
                const int pi = f >> 7;
                pt[l] = slab[cc * K3A_SSTR + (pi / 3) * 66 + (pi % 3) + p];
            }
            uint32_t ov[6];
            #pragma unroll
            for (int m = 0; m < 6; m++) {
                float s = 0.f;
                #pragma unroll
                for (int l = 0; l < 9; l++) s = fmaf(dv[m * 9 + l], pt[l], s);
                ov[m] = tf32_rna(s);
            }
            float2* dst = (float2*)(arow + ch * 6);
            dst[0] = make_float2(__uint_as_float(ov[0]), __uint_as_float(ov[1]));
            dst[1] = make_float2(__uint_as_float(ov[2]), __uint_as_float(ov[3]));
            dst[2] = make_float2(__uint_as_float(ov[4]), __uint_as_float(ov[5]));
        }
    }
}

// ===========================================================================
// Kernel 3b: mma.sync tf32 GEMM out[65536,256] = A x B^T + bias  (passing, R9)
// grid = 512 (mt), block 512 (16 warps, 4m x 4n); block tile 128x256.
// ===========================================================================
#define K3B_STR  36
#define K3B_ACH  (128 * K3B_STR)
#define K3B_BCH  (256 * K3B_STR)
#define K3B_SMEM ((2 * K3B_ACH + 2 * K3B_BCH) * 4)

__global__ __launch_bounds__(512, 1)
void k3b_kernel(const float* __restrict__ bias, float* __restrict__ out) {
    extern __shared__ float sm[];
    float* As[2] = { sm,              sm + K3B_ACH };
    float* Bs[2] = { sm + 2 * K3B_ACH, sm + 2 * K3B_ACH + K3B_BCH };

    const int t    = threadIdx.x;
    const int mt   = blockIdx.x;
    const int wid  = t >> 5;
    const int lane = t & 31;
    const int g    = lane >> 2;
    const int tid4 = lane & 3;

    const float* Abase = g_A + (size_t)(mt << 7) * 768;

    for (int i = t; i < 1024; i += 512) {
        int row = i >> 3, seg = i & 7;
        cp_async16(As[0] + row * K3B_STR + seg * 4, Abase + row * 768 + seg * 4);
    }
    for (int i = t; i < 2048; i += 512) {
        int row = i >> 3, seg = i & 7;
        cp_async16(Bs[0] + row * K3B_STR + seg * 4, g_Bt + row * 768 + seg * 4);
    }
    cp_commit();

    const int wm = wid >> 2, wn = wid & 3;
    const int m0 = wm << 5, n0 = wn << 6;
    float d[2][8][4] = {};

    for (int kc = 0; kc < 24; kc++) {
        cp_wait<0>();
        __syncthreads();
        if (kc < 23) {
            const int nc = kc + 1, buf = nc & 1;
            const float* as = Abase + nc * 32;
            const float* bs = g_Bt + nc * 32;
            for (int i = t; i < 1024; i += 512) {
                int row = i >> 3, seg = i & 7;
                cp_async16(As[buf] + row * K3B_STR + seg * 4, as + row * 768 + seg * 4);
            }
            for (int i = t; i < 2048; i += 512) {
                int row = i >> 3, seg = i & 7;
                cp_async16(Bs[buf] + row * K3B_STR + seg * 4, bs + row * 768 + seg * 4);
            }
            cp_commit();
        }
        const float* Ac = As[kc & 1];
        const float* Bc = Bs[kc & 1];

        #pragma unroll
        for (int kt = 0; kt < 4; kt++) {
            const int k0 = kt << 3;
            uint32_t a[2][4], b[8][2];
            #pragma unroll
            for (int mi = 0; mi < 2; mi++) {
                const float* ap = Ac + (m0 + (mi << 4) + g) * K3B_STR + k0 + tid4;
                a[mi][0] = __float_as_uint(ap[0]);
                a[mi][1] = __float_as_uint(ap[8 * K3B_STR]);
                a[mi][2] = __float_as_uint(ap[4]);
                a[mi][3] = __float_as_uint(ap[8 * K3B_STR + 4]);
            }
            #pragma unroll
            for (int ni = 0; ni < 8; ni++) {
                const float* bp = Bc + (n0 + (ni << 3) + g) * K3B_STR + k0 + tid4;
                b[ni][0] = __float_as_uint(bp[0]);
                b[ni][1] = __float_as_uint(bp[4]);
            }
            #pragma unroll
            for (int mi = 0; mi < 2; mi++)
                #pragma unroll
                for (int ni = 0; ni < 8; ni++)
                    mma_tf32(d[mi][ni], a[mi], b[ni]);
        }
        __syncthreads();
    }

    const size_t rbase = (size_t)(mt << 7) + m0;
    const int    cbase = n0 + (tid4 << 1);
    #pragma unroll
    for (int mi = 0; mi < 2; mi++) {
        float* r0 = out + (rbase + (mi << 4) + g) * OO;
        float* r1 = r0 + 8 * OO;
        #pragma unroll
        for (int ni = 0; ni < 8; ni++) {
            const int c = cbase + (ni << 3);
            const float b0 = bias[c], b1 = bias[c + 1];
            *(float2*)(r0 + c) = make_float2(d[mi][ni][0] + b0, d[mi][ni][1] + b1);
            *(float2*)(r1 + c) = make_float2(d[mi][ni][2] + b0, d[mi][ni][3] + b1);
        }
    }
}

// ===========================================================================
extern "C" void kernel_launch(void* const* d_in, const int* in_sizes, int n_in,
                              void* d_out, int out_size) {
    const float* x      = (const float*)d_in[0];
    const float* w1     = (const float*)d_in[1];
    const float* b1     = (const float*)d_in[2];
    const float* gamma1 = (const float*)d_in[3];
    const float* beta1  = (const float*)d_in[4];
    const float* w2     = (const float*)d_in[5];
    const float* b2     = (const float*)d_in[6];
    const float* gamma2 = (const float*)d_in[7];
    const float* beta2  = (const float*)d_in[8];
    const float* bases  = (const float*)d_in[9];
    const float* coef   = (const float*)d_in[10];
    const float* bias   = (const float*)d_in[11];
    float* out = (float*)d_out;

    cudaFuncSetAttribute(conv1_kernel, cudaFuncAttributeMaxDynamicSharedMemorySize, C1_SMEM);
    cudaFuncSetAttribute(conv2_kernel, cudaFuncAttributeMaxDynamicSharedMemorySize, C2_SMEM);
    cudaFuncSetAttribute(k3a_kernel,   cudaFuncAttributeMaxDynamicSharedMemorySize, K3A_SMEM);
    cudaFuncSetAttribute(k3b_kernel,   cudaFuncAttributeMaxDynamicSharedMemorySize, K3B_SMEM);

    prepW_kernel <<<576, 128>>>(w1);
    prepW2_kernel<<<48,  576>>>(w2);
    prepB_kernel <<<OO,  256>>>(coef);
    conv1_kernel<<<NB * HH / 2, 256, C1_SMEM>>>(x, b1, gamma1, beta1);
    conv2_kernel<<<NB * HH / 4, 512, C2_SMEM>>>(b2, gamma2, beta2, bases);
    k3a_kernel  <<<NB * HH,     256, K3A_SMEM>>>(x);
    k3b_kernel  <<<512,         512, K3B_SMEM>>>(bias, out);
}